// round 5
// baseline (speedup 1.0000x reference)
#include <cuda_runtime.h>
#include <cstdint>

// ChebyshevEncoder fused kernel v4 for GB300 (sm_103a)
//
// 4-CTA cluster = one batch-row worker; CTA rank h owns head h.
// 1024 threads/CTA: thread t = (feature i = t>>1, k-half = t&1).
// v4: LN reduction deferred out of the hot loop.
//   - compute loop per row: cheb + FFMA2 half-matvec + tanh-silu,
//     STS.128 acts + STS.64 raw (sum,sq). No shfl in the loop.
//   - once per 8-row batch: 4 warps/row sum 1024 float2s via add.f32x2,
//     one shfl chain, DSMEM broadcast + barrier.cluster, mean/rstd.
//   - epilogue: normalize from smem, coalesced STG.128.

#define TPB          1024
#define NUM_CLUSTERS 32
#define NBLK         (NUM_CLUSTERS * 4)
#define ROWS_ITER    8
#define NBATCH       (4096 / ROWS_ITER)          // 512 row-batches

// smem layout (floats)
#define SMEM_A       0                            // [8][1024] float4 = 32768 floats
#define SMEM_RED     (SMEM_A + ROWS_ITER * TPB * 4)    // [8][1024] float2 = 16384
#define SMEM_RED2    (SMEM_RED + ROWS_ITER * TPB * 2)  // [8][4] float2 = 64
#define SMEM_PAR     (SMEM_RED2 + 64)             // 2 parity * 4 ranks * 16 = 128
#define SMEM_MR      (SMEM_PAR + 128)             // 8 rows * float2 = 16
#define SMEM_FLOATS  (SMEM_MR + 16)
#define SMEM_BYTES   (SMEM_FLOATS * 4)            // 197,440 B

typedef unsigned long long ull;

__device__ __forceinline__ ull pack2(float lo, float hi) {
    ull r; asm("mov.b64 %0, {%1, %2};" : "=l"(r) : "f"(lo), "f"(hi)); return r;
}
__device__ __forceinline__ void unpack2(ull v, float& lo, float& hi) {
    asm("mov.b64 {%0, %1}, %2;" : "=f"(lo), "=f"(hi) : "l"(v));
}
__device__ __forceinline__ ull ffma2(ull a, ull b, ull c) {
    ull d; asm("fma.rn.f32x2 %0, %1, %2, %3;" : "=l"(d) : "l"(a), "l"(b), "l"(c)); return d;
}
__device__ __forceinline__ ull fadd2(ull a, ull b) {
    ull d; asm("add.rn.f32x2 %0, %1, %2;" : "=l"(d) : "l"(a), "l"(b)); return d;
}
__device__ __forceinline__ float tanhf_hw(float x) {
    float r; asm("tanh.approx.f32 %0, %1;" : "=f"(r) : "f"(x)); return r;
}
__device__ __forceinline__ uint32_t smem_u32(const void* p) {
    return (uint32_t)__cvta_generic_to_shared(p);
}
__device__ __forceinline__ void st_remote_f32(uint32_t laddr, uint32_t rank, float v) {
    uint32_t raddr;
    asm volatile("mapa.shared::cluster.u32 %0, %1, %2;" : "=r"(raddr) : "r"(laddr), "r"(rank));
    asm volatile("st.shared::cluster.f32 [%0], %1;" :: "r"(raddr), "f"(v) : "memory");
}
__device__ __forceinline__ void cluster_sync() {
    asm volatile("barrier.cluster.arrive.aligned;" ::: "memory");
    asm volatile("barrier.cluster.wait.aligned;" ::: "memory");
}

__global__ void __launch_bounds__(TPB, 1) __cluster_dims__(4, 1, 1)
cheb_fused_kernel(const float* __restrict__ x,
                  const float* __restrict__ scale,
                  const float* __restrict__ poly,
                  const float* __restrict__ kern,
                  const float* __restrict__ gamma,
                  const float* __restrict__ beta,
                  float* __restrict__ out)
{
    extern __shared__ float sm[];
    const int tid   = threadIdx.x;
    const int lane  = tid & 31;
    const int wid   = tid >> 5;                   // 0..31
    const int feat  = tid >> 1;                   // feature within head
    const int khalf = tid & 1;                    // which 4 of the 8 k-cols
    uint32_t h;
    asm("mov.u32 %0, %%cluster_ctarank;" : "=r"(h));
    const int cid = blockIdx.x >> 2;

    // ---- one-time preload: folded half-row weights (f32x2 packed) + scale ----
    ull W2[8][2];
    const float sc = scale[feat];
    {
        const float4* kp = (const float4*)kern + ((size_t)h * 512 + feat) * 16 + khalf;
        const float4  pv = ((const float4*)poly)[((size_t)h * 512 + feat) * 2 + khalf];
        #pragma unroll
        for (int m = 0; m < 8; m++) {
            float4 a = kp[m * 2];
            W2[m][0] = pack2(a.x * pv.x, a.y * pv.y);
            W2[m][1] = pack2(a.z * pv.z, a.w * pv.w);
        }
    }

    cluster_sync();  // peers launched; DSMEM slots safe to target

    int parity = 0;
    const float invN = 1.0f / 16384.0f;

    // prefetch x for first row of first batch
    float xnext = x[(size_t)(cid * ROWS_ITER) * 512 + feat];

    for (int batch = cid; batch < NBATCH; batch += NUM_CLUSTERS) {
        const int row0 = batch * ROWS_ITER;

        // ---- compute phase: 8 rows; no reductions in the loop ----
        float4* ap = (float4*)(sm + SMEM_A) + tid;
        float2* rp = (float2*)(sm + SMEM_RED) + tid;
        #pragma unroll 1
        for (int r = 0; r < ROWS_ITER; r++) {
            const float xv = xnext;
            {
                int nb = batch + NUM_CLUSTERS;
                int nrow = (r < ROWS_ITER - 1) ? (row0 + r + 1)
                         : ((nb < NBATCH) ? nb * ROWS_ITER : row0);
                xnext = x[(size_t)nrow * 512 + feat];
            }

            const float xs = xv * sc;
            // Chebyshev T1..T7 packed (T0 == 1 folded into acc init)
            ull t2[7];
            {
                const float x2 = xs + xs;
                float tm2 = 1.0f, tm1 = xs;
                t2[0] = pack2(xs, xs);
                #pragma unroll
                for (int m = 2; m < 8; m++) {
                    const float T = fmaf(x2, tm1, -tm2);
                    tm2 = tm1; tm1 = T;
                    t2[m - 1] = pack2(T, T);
                }
            }
            // 8x4 half-matvec as 2 f32x2 accumulators
            ull acc0 = W2[0][0], acc1 = W2[0][1];
            #pragma unroll
            for (int m = 0; m < 7; m++) {
                acc0 = ffma2(t2[m], W2[m + 1][0], acc0);
                acc1 = ffma2(t2[m], W2[m + 1][1], acc1);
            }

            // silu via tanh: v = b*(1+tanh(b)), b = a/2
            float a0, a1, a2, a3;
            unpack2(acc0, a0, a1);
            unpack2(acc1, a2, a3);
            const float b0 = 0.5f * a0, b1 = 0.5f * a1;
            const float b2 = 0.5f * a2, b3 = 0.5f * a3;
            const float v0 = fmaf(tanhf_hw(b0), b0, b0);
            const float v1 = fmaf(tanhf_hw(b1), b1, b1);
            const float v2 = fmaf(tanhf_hw(b2), b2, b2);
            const float v3 = fmaf(tanhf_hw(b3), b3, b3);

            const float sum = (v0 + v1) + (v2 + v3);
            const float sq  = fmaf(v0, v0, fmaf(v1, v1, fmaf(v2, v2, v3 * v3)));

            *ap = make_float4(v0, v1, v2, v3);     ap += TPB;
            *rp = make_float2(sum, sq);            rp += TPB;
        }
        __syncthreads();

        // ---- batch stats: 4 warps per row reduce 1024 (sum,sq) pairs ----
        {
            const int row = wid >> 2;                       // 0..7
            const int j   = ((wid & 3) << 5) | lane;        // 0..127
            const ull* sp = (const ull*)(sm + SMEM_RED) + row * TPB + j;
            ull s2 = sp[0];
            #pragma unroll
            for (int q = 1; q < 8; q++) s2 = fadd2(s2, sp[q * 128]);
            float s, q;
            unpack2(s2, s, q);
            #pragma unroll
            for (int o = 16; o > 0; o >>= 1) {
                s += __shfl_xor_sync(0xffffffffu, s, o);
                q += __shfl_xor_sync(0xffffffffu, q, o);
            }
            if (lane == 0)
                ((float2*)(sm + SMEM_RED2))[row * 4 + (wid & 3)] = make_float2(s, q);
        }
        __syncthreads();

        // ---- CTA partials -> broadcast to all 4 cluster CTAs via DSMEM ----
        if (tid < 16) {
            // tid = row*2 + comp (comp: 0=sum, 1=sq)
            const float* r2 = sm + SMEM_RED2 + (tid >> 1) * 8 + (tid & 1);
            const float acc = (r2[0] + r2[2]) + (r2[4] + r2[6]);
            const uint32_t laddr = smem_u32(sm + SMEM_PAR + parity * 64 + h * 16 + tid);
            #pragma unroll
            for (uint32_t dst = 0; dst < 4; dst++) st_remote_f32(laddr, dst, acc);
        }
        cluster_sync();  // release remote stores / acquire peers' partials

        // ---- per-row mean / rstd (redundantly in every CTA) ----
        if (tid < 8) {
            const float* par = sm + SMEM_PAR + parity * 64;
            float s = 0.f, q = 0.f;
            #pragma unroll
            for (int rk = 0; rk < 4; rk++) {
                s += par[rk * 16 + 2 * tid];
                q += par[rk * 16 + 2 * tid + 1];
            }
            const float mean = s * invN;
            const float var  = fmaf(-mean, mean, q * invN);
            const float rstd = rsqrtf(var + 1e-5f);
            ((float2*)(sm + SMEM_MR))[tid] = make_float2(rstd, -mean * rstd);
        }
        __syncthreads();

        // ---- normalize + coalesced store ----
        const float4 gv = __ldg((const float4*)(gamma + (size_t)h * 4096) + tid);
        const float4 bv = __ldg((const float4*)(beta  + (size_t)h * 4096) + tid);
        const float4* aq = (const float4*)(sm + SMEM_A) + tid;
        float4* op = (float4*)(out + (size_t)row0 * 16384 + (size_t)h * 4096) + tid;
        #pragma unroll 1
        for (int r = 0; r < ROWS_ITER; r++) {
            const float2 mr = ((const float2*)(sm + SMEM_MR))[r];
            const float4 va = *aq;  aq += TPB;
            float4 o;
            o.x = fmaf(fmaf(va.x, mr.x, mr.y), gv.x, bv.x);
            o.y = fmaf(fmaf(va.y, mr.x, mr.y), gv.y, bv.y);
            o.z = fmaf(fmaf(va.z, mr.x, mr.y), gv.z, bv.z);
            o.w = fmaf(fmaf(va.w, mr.x, mr.y), gv.w, bv.w);
            *op = o;  op += 4096;
        }
        parity ^= 1;
    }
}

extern "C" void kernel_launch(void* const* d_in, const int* in_sizes, int n_in,
                              void* d_out, int out_size)
{
    const float* x     = (const float*)d_in[0];   // [4096, 512]
    const float* scale = (const float*)d_in[1];   // [512]
    const float* poly  = (const float*)d_in[2];   // [4, 512, 8]
    const float* kern  = (const float*)d_in[3];   // [4, 512, 8, 8]
    const float* gamma = (const float*)d_in[4];   // [16384]
    const float* beta  = (const float*)d_in[5];   // [16384]
    float* out = (float*)d_out;                   // [4096, 16384]

    (void)in_sizes; (void)n_in; (void)out_size;

    cudaFuncSetAttribute(cheb_fused_kernel,
                         cudaFuncAttributeMaxDynamicSharedMemorySize, SMEM_BYTES);

    cheb_fused_kernel<<<NBLK, TPB, SMEM_BYTES, 0>>>(x, scale, poly, kern, gamma, beta, out);
}

// round 7
// speedup vs baseline: 1.2139x; 1.2139x over previous
#include <cuda_runtime.h>
#include <cstdint>

// ChebyshevEncoder fused kernel v5 for GB300 (sm_103a)
//
// 4-CTA cluster = one batch-row worker; CTA rank h owns head h.
// 1024 threads/CTA: thread t = (feature i = t>>1, k-half = t&1), 16 weight
// regs (f32x2 packs) -> ~64 regs/thread -> 32 warps/SM.
//
// v5: software-pipelined batches. The normalize+store epilogue of batch b-1
// is fused row-by-row into the compute loop of batch b (same thread owns
// the smem act slot for both -> no double buffer, no extra syncs). Memory
// ops of the epilogue hide under FMA/MUFU of the compute, and the separate
// low-ILP epilogue phase disappears. gamma/beta served from smem (one-time
// copy) to keep regs <= 64. Output stores use st.global.cs (write-once).

#define TPB          1024
#define NUM_CLUSTERS 32
#define NBLK         (NUM_CLUSTERS * 4)
#define ROWS_ITER    8
#define NBATCH       (4096 / ROWS_ITER)          // 512 row-batches

// smem layout (floats)
#define SMEM_A       0                                 // [8][1024] float4 = 32768
#define SMEM_RED     (SMEM_A + ROWS_ITER * TPB * 4)    // 32 warps * 16 = 512
#define SMEM_PAR     (SMEM_RED + 512)                  // 2 parity * 4 ranks * 16 = 128
#define SMEM_MR      (SMEM_PAR + 128)                  // 8 rows * float2 = 16
#define SMEM_G       (SMEM_MR + 16)                    // [1024] float4 = 4096
#define SMEM_B       (SMEM_G + TPB * 4)                // [1024] float4 = 4096
#define SMEM_FLOATS  (SMEM_B + TPB * 4)
#define SMEM_BYTES   (SMEM_FLOATS * 4)                 // 166,464 B

typedef unsigned long long ull;

__device__ __forceinline__ ull pack2(float lo, float hi) {
    ull r; asm("mov.b64 %0, {%1, %2};" : "=l"(r) : "f"(lo), "f"(hi)); return r;
}
__device__ __forceinline__ void unpack2(ull v, float& lo, float& hi) {
    asm("mov.b64 {%0, %1}, %2;" : "=f"(lo), "=f"(hi) : "l"(v));
}
__device__ __forceinline__ ull ffma2(ull a, ull b, ull c) {
    ull d; asm("fma.rn.f32x2 %0, %1, %2, %3;" : "=l"(d) : "l"(a), "l"(b), "l"(c)); return d;
}
__device__ __forceinline__ float tanhf_hw(float x) {
    float r; asm("tanh.approx.f32 %0, %1;" : "=f"(r) : "f"(x)); return r;
}
__device__ __forceinline__ uint32_t smem_u32(const void* p) {
    return (uint32_t)__cvta_generic_to_shared(p);
}
__device__ __forceinline__ void st_remote_f32(uint32_t laddr, uint32_t rank, float v) {
    uint32_t raddr;
    asm volatile("mapa.shared::cluster.u32 %0, %1, %2;" : "=r"(raddr) : "r"(laddr), "r"(rank));
    asm volatile("st.shared::cluster.f32 [%0], %1;" :: "r"(raddr), "f"(v) : "memory");
}
__device__ __forceinline__ void cluster_sync() {
    asm volatile("barrier.cluster.arrive.aligned;" ::: "memory");
    asm volatile("barrier.cluster.wait.aligned;" ::: "memory");
}

__global__ void __launch_bounds__(TPB, 1) __cluster_dims__(4, 1, 1)
cheb_fused_kernel(const float* __restrict__ x,
                  const float* __restrict__ scale,
                  const float* __restrict__ poly,
                  const float* __restrict__ kern,
                  const float* __restrict__ gamma,
                  const float* __restrict__ beta,
                  float* __restrict__ out)
{
    extern __shared__ float sm[];
    const int tid   = threadIdx.x;
    const int lane  = tid & 31;
    const int wid   = tid >> 5;                   // 0..31
    const int feat  = tid >> 1;                   // feature within head
    const int khalf = tid & 1;                    // which 4 of the 8 k-cols
    uint32_t h;
    asm("mov.u32 %0, %%cluster_ctarank;" : "=r"(h));
    const int cid = blockIdx.x >> 2;

    // ---- one-time preload: folded half-row weights (f32x2 packed) + scale ----
    ull W2[8][2];
    const float sc = scale[feat];
    {
        const float4* kp = (const float4*)kern + ((size_t)h * 512 + feat) * 16 + khalf;
        const float4  pv = ((const float4*)poly)[((size_t)h * 512 + feat) * 2 + khalf];
        #pragma unroll
        for (int m = 0; m < 8; m++) {
            float4 a = kp[m * 2];
            W2[m][0] = pack2(a.x * pv.x, a.y * pv.y);
            W2[m][1] = pack2(a.z * pv.z, a.w * pv.w);
        }
    }
    // gamma/beta slices -> smem (read each batch via LDS.128, keeps regs <= 64)
    ((float4*)(sm + SMEM_G))[tid] = __ldg((const float4*)(gamma + (size_t)h * 4096) + tid);
    ((float4*)(sm + SMEM_B))[tid] = __ldg((const float4*)(beta  + (size_t)h * 4096) + tid);

    cluster_sync();  // peers launched; DSMEM slots safe to target

    int parity = 0;
    int prev_row0 = 0;
    const float invN = 1.0f / 16384.0f;

    // prefetch x for first row of first batch
    float xnext = x[(size_t)(cid * ROWS_ITER) * 512 + feat];

    #pragma unroll 1
    for (int it = 0; ; ++it) {
        const int batch = cid + it * NUM_CLUSTERS;
        const bool comp = (batch < NBATCH);
        const int row0 = batch * ROWS_ITER;

        float4* ap = (float4*)(sm + SMEM_A) + tid;
        float4* op = (float4*)(out + (size_t)prev_row0 * 16384 + (size_t)h * 4096) + tid;

        // ---- fused loop: epilogue(prev batch) + compute(this batch), per row ----
        #pragma unroll 1
        for (int r = 0; r < ROWS_ITER; r++) {
            if (it > 0) {
                // normalize + store row r of previous batch (thread-private slot)
                const float2 mr = ((const float2*)(sm + SMEM_MR))[r];
                const float4 va = *ap;
                const float4 gv = ((const float4*)(sm + SMEM_G))[tid];
                const float4 bvv = ((const float4*)(sm + SMEM_B))[tid];
                float4 o;
                o.x = fmaf(fmaf(va.x, mr.x, mr.y), gv.x, bvv.x);
                o.y = fmaf(fmaf(va.y, mr.x, mr.y), gv.y, bvv.y);
                o.z = fmaf(fmaf(va.z, mr.x, mr.y), gv.z, bvv.z);
                o.w = fmaf(fmaf(va.w, mr.x, mr.y), gv.w, bvv.w);
                __stcs(op, o);
                op += 4096;
            }
            if (comp) {
                const float xv = xnext;
                {
                    int nb = batch + NUM_CLUSTERS;
                    int nrow = (r < ROWS_ITER - 1) ? (row0 + r + 1)
                             : ((nb < NBATCH) ? nb * ROWS_ITER : row0);
                    xnext = x[(size_t)nrow * 512 + feat];
                }

                const float xs = xv * sc;
                // Chebyshev T1..T7 packed (T0 == 1 folded into acc init)
                ull t2[7];
                {
                    const float x2 = xs + xs;
                    float tm2 = 1.0f, tm1 = xs;
                    t2[0] = pack2(xs, xs);
                    #pragma unroll
                    for (int m = 2; m < 8; m++) {
                        const float T = fmaf(x2, tm1, -tm2);
                        tm2 = tm1; tm1 = T;
                        t2[m - 1] = pack2(T, T);
                    }
                }
                // 8x4 half-matvec as 2 f32x2 accumulators
                ull acc0 = W2[0][0], acc1 = W2[0][1];
                #pragma unroll
                for (int m = 0; m < 7; m++) {
                    acc0 = ffma2(t2[m], W2[m + 1][0], acc0);
                    acc1 = ffma2(t2[m], W2[m + 1][1], acc1);
                }

                // silu via tanh: v = b*(1+tanh(b)), b = a/2
                float a0, a1, a2, a3;
                unpack2(acc0, a0, a1);
                unpack2(acc1, a2, a3);
                const float b0 = 0.5f * a0, b1 = 0.5f * a1;
                const float b2 = 0.5f * a2, b3 = 0.5f * a3;
                const float v0 = fmaf(tanhf_hw(b0), b0, b0);
                const float v1 = fmaf(tanhf_hw(b1), b1, b1);
                const float v2 = fmaf(tanhf_hw(b2), b2, b2);
                const float v3 = fmaf(tanhf_hw(b3), b3, b3);

                float sum = (v0 + v1) + (v2 + v3);
                float sq  = fmaf(v0, v0, fmaf(v1, v1, fmaf(v2, v2, v3 * v3)));

                *ap = make_float4(v0, v1, v2, v3);   // overwrite own slot (safe)

                // warp reduce this row's (sum, sq)
                #pragma unroll
                for (int o = 16; o > 0; o >>= 1) {
                    sum += __shfl_xor_sync(0xffffffffu, sum, o);
                    sq  += __shfl_xor_sync(0xffffffffu, sq,  o);
                }
                if (lane == 0) {
                    sm[SMEM_RED + wid * 16 + 2 * r]     = sum;
                    sm[SMEM_RED + wid * 16 + 2 * r + 1] = sq;
                }
            }
            ap += TPB;
        }

        if (!comp) break;   // flushed last epilogue; done
        __syncthreads();

        // ---- CTA partials -> broadcast to all 4 cluster CTAs via DSMEM ----
        if (tid < 16) {
            float acc = 0.f;
            #pragma unroll
            for (int w = 0; w < 32; w++) acc += sm[SMEM_RED + w * 16 + tid];
            const uint32_t laddr = smem_u32(sm + SMEM_PAR + parity * 64 + h * 16 + tid);
            #pragma unroll
            for (uint32_t dst = 0; dst < 4; dst++) st_remote_f32(laddr, dst, acc);
        }
        cluster_sync();  // release remote stores / acquire peers' partials

        // ---- per-row mean / rstd (redundantly in every CTA) ----
        if (tid < 8) {
            const float* par = sm + SMEM_PAR + parity * 64;
            float s = 0.f, q = 0.f;
            #pragma unroll
            for (int rk = 0; rk < 4; rk++) {
                s += par[rk * 16 + 2 * tid];
                q += par[rk * 16 + 2 * tid + 1];
            }
            const float mean = s * invN;
            const float var  = fmaf(-mean, mean, q * invN);
            const float rstd = rsqrtf(var + 1e-5f);
            ((float2*)(sm + SMEM_MR))[tid] = make_float2(rstd, -mean * rstd);
        }
        __syncthreads();

        prev_row0 = row0;
        parity ^= 1;
    }
}

extern "C" void kernel_launch(void* const* d_in, const int* in_sizes, int n_in,
                              void* d_out, int out_size)
{
    const float* x     = (const float*)d_in[0];   // [4096, 512]
    const float* scale = (const float*)d_in[1];   // [512]
    const float* poly  = (const float*)d_in[2];   // [4, 512, 8]
    const float* kern  = (const float*)d_in[3];   // [4, 512, 8, 8]
    const float* gamma = (const float*)d_in[4];   // [16384]
    const float* beta  = (const float*)d_in[5];   // [16384]
    float* out = (float*)d_out;                   // [4096, 16384]

    (void)in_sizes; (void)n_in; (void)out_size;

    cudaFuncSetAttribute(cheb_fused_kernel,
                         cudaFuncAttributeMaxDynamicSharedMemorySize, SMEM_BYTES);

    cheb_fused_kernel<<<NBLK, TPB, SMEM_BYTES, 0>>>(x, scale, poly, kern, gamma, beta, out);
}